// round 1
// baseline (speedup 1.0000x reference)
#include <cuda_runtime.h>
#include <math.h>

// Problem constants (fixed shapes)
#define NN 100000
#define NE 1600000
#define NG 512
#define FIN 128
#define HH 64
#define HS 192   // 3*H concat width
#define GF 576   // 3*HS graph feature width

// ---------------- scratch (static device globals; no runtime alloc) -------
__device__ __align__(16) float g_agg[(size_t)NN * FIN];   // 51.2 MB
__device__ __align__(16) float g_hs[(size_t)NN * HS];     // 76.8 MB
__device__ int g_cnt[NG];
__device__ int g_off[NG + 1];
__device__ int g_is64;

// ---------------- index dtype handling -------------------------------------
__device__ __forceinline__ long ld_idx(const void* p, long i) {
    if (g_is64) return (long)((const long long*)p)[i];
    return (long)((const int*)p)[i];
}

__global__ void k_detect(const void* edge) {
    if (threadIdx.x == 0 && blockIdx.x == 0) {
        // int64 indices < 2^31 => every odd 32-bit word is zero.
        const int* p = (const int*)edge;
        int is64 = 1;
        for (int i = 0; i < 64; i++) {
            if (p[2 * i + 1] != 0) { is64 = 0; break; }
        }
        g_is64 = is64;
    }
}

// ---------------- zero helpers ---------------------------------------------
__global__ void k_zero_agg(int n4) {
    int i = blockIdx.x * 256 + threadIdx.x;
    if (i < n4) ((float4*)g_agg)[i] = make_float4(0.f, 0.f, 0.f, 0.f);
}

__global__ void k_zero_cnt() {
    int i = blockIdx.x * 256 + threadIdx.x;
    if (i < NG) g_cnt[i] = 0;
}

// ---------------- scatter-add (segment_sum of x[src] into dst) -------------
// One edge is handled by F/4 consecutive threads; each does a float4 gather
// and a vectorized no-return reduction (red.global.add.v4.f32).
template <int F>
__global__ void __launch_bounds__(256) k_scatter(const float* __restrict__ x,
                                                 const void* __restrict__ edge,
                                                 int use_x, int in_off) {
    constexpr int C = F / 4;            // float4 chunks per edge
    long idx = (long)blockIdx.x * 256 + threadIdx.x;
    if (idx >= (long)NE * C) return;
    long e = idx / C;
    int  c = (int)(idx - e * C);

    long s = ld_idx(edge, e);
    long d = ld_idx(edge, (long)NE + e);

    const float* in = use_x ? x : (g_hs + in_off);
    const int stride = use_x ? FIN : HS;

    float4 v = *(const float4*)&in[s * stride + c * 4];
    float* dst = &g_agg[d * (long)F + c * 4];
    asm volatile("red.global.add.v4.f32 [%0], {%1, %2, %3, %4};"
                 :: "l"(dst), "f"(v.x), "f"(v.y), "f"(v.z), "f"(v.w)
                 : "memory");
}

// ---------------- fused GIN MLP: h = relu(relu(((1+eps)x+agg)W1+b1)W2+b2) ---
// Tile: 64 nodes x 64 outputs, 256 threads as 16x16, 4x4 microtiles.
// h1 lives only in shared memory; output goes straight into the hs concat.
__global__ void __launch_bounds__(256) k_mlp(const float* __restrict__ x,
                                             int use_x, int in_off, int fin,
                                             const float* __restrict__ eps, int layer,
                                             const float* __restrict__ W1,
                                             const float* __restrict__ B1,
                                             const float* __restrict__ W2,
                                             const float* __restrict__ B2,
                                             int out_off) {
    __shared__ float sA[64][68];
    __shared__ float sB[64][68];

    const int tid = threadIdx.x;
    const int tx = tid & 15;
    const int ty = tid >> 4;
    const int tile = blockIdx.x * 64;

    const float* in = use_x ? x : (g_hs + in_off);
    const int in_stride = use_x ? FIN : HS;
    const float epsv = 1.0f + eps[layer];

    float4 c0 = make_float4(0.f, 0.f, 0.f, 0.f), c1 = c0, c2 = c0, c3 = c0;

    for (int kc = 0; kc < fin; kc += 64) {
        // Stage P chunk (p = (1+eps)*x + agg) and W1 chunk into smem.
#pragma unroll
        for (int s = 0; s < 4; s++) {
            int slot = tid + s * 256;       // 0..1023
            int r  = slot >> 4;             // 0..63
            int k4 = slot & 15;             // float4 within 64-wide chunk
            int rg = tile + r;
            float4 v = make_float4(0.f, 0.f, 0.f, 0.f);
            if (rg < NN) {
                float4 xv = *(const float4*)&in[(long)rg * in_stride + kc + k4 * 4];
                float4 av = *(const float4*)&g_agg[(long)rg * fin + kc + k4 * 4];
                v.x = epsv * xv.x + av.x;
                v.y = epsv * xv.y + av.y;
                v.z = epsv * xv.z + av.z;
                v.w = epsv * xv.w + av.w;
            }
            *(float4*)&sA[r][k4 * 4] = v;
            *(float4*)&sB[r][k4 * 4] = *(const float4*)&W1[(long)(kc + r) * 64 + k4 * 4];
        }
        __syncthreads();
#pragma unroll 8
        for (int k = 0; k < 64; k++) {
            float4 b = *(const float4*)&sB[k][tx * 4];
            float a0 = sA[ty * 4 + 0][k];
            float a1 = sA[ty * 4 + 1][k];
            float a2 = sA[ty * 4 + 2][k];
            float a3 = sA[ty * 4 + 3][k];
            c0.x += a0 * b.x; c0.y += a0 * b.y; c0.z += a0 * b.z; c0.w += a0 * b.w;
            c1.x += a1 * b.x; c1.y += a1 * b.y; c1.z += a1 * b.z; c1.w += a1 * b.w;
            c2.x += a2 * b.x; c2.y += a2 * b.y; c2.z += a2 * b.z; c2.w += a2 * b.w;
            c3.x += a3 * b.x; c3.y += a3 * b.y; c3.z += a3 * b.z; c3.w += a3 * b.w;
        }
        __syncthreads();
    }

    // h1 = relu(c + b1) -> sA  (safe: all threads passed the trailing sync)
    {
        float4 bb = *(const float4*)&B1[tx * 4];
        float4 h;
        h.x = fmaxf(c0.x + bb.x, 0.f); h.y = fmaxf(c0.y + bb.y, 0.f);
        h.z = fmaxf(c0.z + bb.z, 0.f); h.w = fmaxf(c0.w + bb.w, 0.f);
        *(float4*)&sA[ty * 4 + 0][tx * 4] = h;
        h.x = fmaxf(c1.x + bb.x, 0.f); h.y = fmaxf(c1.y + bb.y, 0.f);
        h.z = fmaxf(c1.z + bb.z, 0.f); h.w = fmaxf(c1.w + bb.w, 0.f);
        *(float4*)&sA[ty * 4 + 1][tx * 4] = h;
        h.x = fmaxf(c2.x + bb.x, 0.f); h.y = fmaxf(c2.y + bb.y, 0.f);
        h.z = fmaxf(c2.z + bb.z, 0.f); h.w = fmaxf(c2.w + bb.w, 0.f);
        *(float4*)&sA[ty * 4 + 2][tx * 4] = h;
        h.x = fmaxf(c3.x + bb.x, 0.f); h.y = fmaxf(c3.y + bb.y, 0.f);
        h.z = fmaxf(c3.z + bb.z, 0.f); h.w = fmaxf(c3.w + bb.w, 0.f);
        *(float4*)&sA[ty * 4 + 3][tx * 4] = h;
    }
    // Load W2 into sB (64x64, single chunk)
#pragma unroll
    for (int s = 0; s < 4; s++) {
        int slot = tid + s * 256;
        int r  = slot >> 4;
        int k4 = slot & 15;
        *(float4*)&sB[r][k4 * 4] = *(const float4*)&W2[(long)r * 64 + k4 * 4];
    }
    __syncthreads();

    c0 = make_float4(0.f, 0.f, 0.f, 0.f); c1 = c0; c2 = c0; c3 = c0;
#pragma unroll 8
    for (int k = 0; k < 64; k++) {
        float4 b = *(const float4*)&sB[k][tx * 4];
        float a0 = sA[ty * 4 + 0][k];
        float a1 = sA[ty * 4 + 1][k];
        float a2 = sA[ty * 4 + 2][k];
        float a3 = sA[ty * 4 + 3][k];
        c0.x += a0 * b.x; c0.y += a0 * b.y; c0.z += a0 * b.z; c0.w += a0 * b.w;
        c1.x += a1 * b.x; c1.y += a1 * b.y; c1.z += a1 * b.z; c1.w += a1 * b.w;
        c2.x += a2 * b.x; c2.y += a2 * b.y; c2.z += a2 * b.z; c2.w += a2 * b.w;
        c3.x += a3 * b.x; c3.y += a3 * b.y; c3.z += a3 * b.z; c3.w += a3 * b.w;
    }

    {
        float4 bb = *(const float4*)&B2[tx * 4];
        float4 o;
        int rg;
        rg = tile + ty * 4 + 0;
        if (rg < NN) {
            o.x = fmaxf(c0.x + bb.x, 0.f); o.y = fmaxf(c0.y + bb.y, 0.f);
            o.z = fmaxf(c0.z + bb.z, 0.f); o.w = fmaxf(c0.w + bb.w, 0.f);
            *(float4*)&g_hs[(long)rg * HS + out_off + tx * 4] = o;
        }
        rg = tile + ty * 4 + 1;
        if (rg < NN) {
            o.x = fmaxf(c1.x + bb.x, 0.f); o.y = fmaxf(c1.y + bb.y, 0.f);
            o.z = fmaxf(c1.z + bb.z, 0.f); o.w = fmaxf(c1.w + bb.w, 0.f);
            *(float4*)&g_hs[(long)rg * HS + out_off + tx * 4] = o;
        }
        rg = tile + ty * 4 + 2;
        if (rg < NN) {
            o.x = fmaxf(c2.x + bb.x, 0.f); o.y = fmaxf(c2.y + bb.y, 0.f);
            o.z = fmaxf(c2.z + bb.z, 0.f); o.w = fmaxf(c2.w + bb.w, 0.f);
            *(float4*)&g_hs[(long)rg * HS + out_off + tx * 4] = o;
        }
        rg = tile + ty * 4 + 3;
        if (rg < NN) {
            o.x = fmaxf(c3.x + bb.x, 0.f); o.y = fmaxf(c3.y + bb.y, 0.f);
            o.z = fmaxf(c3.z + bb.z, 0.f); o.w = fmaxf(c3.w + bb.w, 0.f);
            *(float4*)&g_hs[(long)rg * HS + out_off + tx * 4] = o;
        }
    }
}

// ---------------- graph segment bookkeeping (batch is sorted) --------------
__global__ void k_count(const void* __restrict__ batch) {
    int i = blockIdx.x * 256 + threadIdx.x;
    if (i < NN) atomicAdd(&g_cnt[(int)ld_idx(batch, i)], 1);
}

__global__ void k_offsets() {
    if (threadIdx.x == 0) {
        int a = 0;
        for (int i = 0; i < NG; i++) { g_off[i] = a; a += g_cnt[i]; }
        g_off[NG] = a;
    }
}

// ---------------- readout: mean/max/sum per graph + fc1 + fc2 + sigmoid ----
__global__ void __launch_bounds__(192) k_readout(const float* __restrict__ fc1w,
                                                 const float* __restrict__ fc1b,
                                                 const float* __restrict__ fc2w,
                                                 const float* __restrict__ fc2b,
                                                 float* __restrict__ out) {
    __shared__ float gv[GF];
    __shared__ float q[HH];

    int g = blockIdx.x;
    int f = threadIdx.x;          // 0..191 — one feature column of hs
    int n0 = g_off[g], n1 = g_off[g + 1];

    float s = 0.f, m = -3.402823466e38f;
    for (int n = n0; n < n1; n++) {
        float v = g_hs[(long)n * HS + f];
        s += v;
        m = fmaxf(m, v);
    }
    int cnt = n1 - n0;
    gv[f]       = s / fmaxf((float)cnt, 1.f);   // mean
    gv[192 + f] = m;                            // max
    gv[384 + f] = s;                            // sum
    __syncthreads();

    if (f < HH) {
        float a = fc1b[f];
#pragma unroll 4
        for (int k = 0; k < GF; k++) a += gv[k] * fc1w[k * 64 + f];
        q[f] = fmaxf(a, 0.f);
    }
    __syncthreads();

    if (f < 2) {
        float a = fc2b[f];
#pragma unroll
        for (int k = 0; k < HH; k++) a += q[k] * fc2w[k * 2 + f];
        out[g * 2 + f] = 1.f / (1.f + expf(-a));
    }
}

// ---------------- launch ----------------------------------------------------
extern "C" void kernel_launch(void* const* d_in, const int* in_sizes, int n_in,
                              void* d_out, int out_size) {
    const float* x     = (const float*)d_in[0];
    const void*  edge  = d_in[1];
    const void*  batch = d_in[2];
    const float* w1[3] = {(const float*)d_in[3],  (const float*)d_in[7],  (const float*)d_in[11]};
    const float* b1[3] = {(const float*)d_in[4],  (const float*)d_in[8],  (const float*)d_in[12]};
    const float* w2[3] = {(const float*)d_in[5],  (const float*)d_in[9],  (const float*)d_in[13]};
    const float* b2[3] = {(const float*)d_in[6],  (const float*)d_in[10], (const float*)d_in[14]};
    const float* eps   = (const float*)d_in[15];
    const float* fc1w  = (const float*)d_in[16];
    const float* fc1b  = (const float*)d_in[17];
    const float* fc2w  = (const float*)d_in[18];
    const float* fc2b  = (const float*)d_in[19];

    k_detect<<<1, 32>>>(edge);

    for (int L = 0; L < 3; L++) {
        const int fin  = (L == 0) ? FIN : HH;
        const int usex = (L == 0) ? 1 : 0;
        const int inoff = (L == 0) ? 0 : (L - 1) * 64;

        const int n4 = NN * fin / 4;
        k_zero_agg<<<(n4 + 255) / 256, 256>>>(n4);

        if (L == 0) {
            long tot = (long)NE * (FIN / 4);
            k_scatter<FIN><<<(int)((tot + 255) / 256), 256>>>(x, edge, 1, 0);
        } else {
            long tot = (long)NE * (HH / 4);
            k_scatter<HH><<<(int)((tot + 255) / 256), 256>>>(x, edge, 0, inoff);
        }

        k_mlp<<<(NN + 63) / 64, 256>>>(x, usex, inoff, fin, eps, L,
                                       w1[L], b1[L], w2[L], b2[L], L * 64);
    }

    k_zero_cnt<<<2, 256>>>();
    k_count<<<(NN + 255) / 256, 256>>>(batch);
    k_offsets<<<1, 32>>>();
    k_readout<<<NG, 192>>>(fc1w, fc1b, fc2w, fc2b, (float*)d_out);
}

// round 3
// speedup vs baseline: 1.1599x; 1.1599x over previous
#include <cuda_runtime.h>
#include <math.h>

// Problem constants (fixed shapes)
#define NN 100000
#define NE 1600000
#define NG 512
#define FIN 128
#define HH 64
#define HS 192   // 3*H concat width
#define GF 576   // 3*HS graph feature width

// ---------------- scratch (static device globals; no runtime alloc) -------
__device__ __align__(16) float g_agg[(size_t)NN * FIN];   // 51.2 MB
__device__ __align__(16) float g_hs[(size_t)NN * HS];     // 76.8 MB
__device__ int g_rowptr[NN + 1];
__device__ int g_cursor[NN];          // also used as degree accumulator
__device__ int g_csr[NE];
__device__ int g_cnt[NG];
__device__ int g_off[NG + 1];
__device__ int g_is64;

// ---------------- index dtype handling -------------------------------------
__device__ __forceinline__ long ld_idx(const void* p, long i) {
    if (g_is64) return (long)((const long long*)p)[i];
    return (long)((const int*)p)[i];
}

__global__ void k_detect(const void* edge) {
    if (threadIdx.x == 0 && blockIdx.x == 0) {
        // int64 indices < 2^31 => every odd 32-bit word is zero.
        const int* p = (const int*)edge;
        int is64 = 1;
        for (int i = 0; i < 64; i++) {
            if (p[2 * i + 1] != 0) { is64 = 0; break; }
        }
        g_is64 = is64;
    }
}

// ---------------- CSR build (once per launch; reused by all 3 layers) ------
__global__ void k_zero_deg() {
    int i = blockIdx.x * 256 + threadIdx.x;
    if (i < NN) g_cursor[i] = 0;
}

__global__ void k_deg(const void* __restrict__ edge) {
    long e = (long)blockIdx.x * 256 + threadIdx.x;
    if (e < NE) {
        int d = (int)ld_idx(edge, (long)NE + e);
        atomicAdd(&g_cursor[d], 1);
    }
}

// Exclusive prefix scan of degrees -> g_rowptr. Single block, 1024 threads.
__global__ void __launch_bounds__(1024) k_scan() {
    __shared__ int s[1024];
    const int t = threadIdx.x;
    const int CH = (NN + 1023) / 1024;     // 98
    const int start = t * CH;
    int sum = 0;
    for (int i = 0; i < CH; i++) {
        int g = start + i;
        if (g < NN) sum += g_cursor[g];
    }
    s[t] = sum;
    __syncthreads();
    for (int d = 1; d < 1024; d <<= 1) {
        int v = (t >= d) ? s[t - d] : 0;
        __syncthreads();
        s[t] += v;
        __syncthreads();
    }
    int off = (t == 0) ? 0 : s[t - 1];
    for (int i = 0; i < CH; i++) {
        int g = start + i;
        if (g < NN) { g_rowptr[g] = off; off += g_cursor[g]; }
    }
    if (t == 1023) g_rowptr[NN] = s[1023];
}

__global__ void k_init_cursor() {
    int i = blockIdx.x * 256 + threadIdx.x;
    if (i < NN) g_cursor[i] = g_rowptr[i];
}

__global__ void k_fill(const void* __restrict__ edge) {
    long e = (long)blockIdx.x * 256 + threadIdx.x;
    if (e < NE) {
        int s = (int)ld_idx(edge, e);
        int d = (int)ld_idx(edge, (long)NE + e);
        int pos = atomicAdd(&g_cursor[d], 1);
        g_csr[pos] = s;
    }
}

// ---------------- pull-aggregation (replaces atomic scatter) ----------------
// One warp per destination node: sum neighbor feature rows with plain loads.
// Input pointer resolved ON DEVICE (device globals are not addressable from
// host code — that was the round-2 bug).
template <int F>
__global__ void __launch_bounds__(256) k_pull(const float* __restrict__ x,
                                              int use_x, int in_off) {
    const float* in = use_x ? x : (g_hs + in_off);
    const int stride = use_x ? FIN : HS;

    int warp = (blockIdx.x * 256 + threadIdx.x) >> 5;
    int lane = threadIdx.x & 31;
    if (warp >= NN) return;
    int beg = g_rowptr[warp], end = g_rowptr[warp + 1];

    if (F == 128) {
        float4 acc = make_float4(0.f, 0.f, 0.f, 0.f);
        for (int j = beg; j < end; j += 32) {
            int n = min(32, end - j);
            int idx = (lane < n) ? g_csr[j + lane] : 0;
            int t = 0;
            for (; t + 4 <= n; t += 4) {
                int u0 = __shfl_sync(0xffffffffu, idx, t + 0);
                int u1 = __shfl_sync(0xffffffffu, idx, t + 1);
                int u2 = __shfl_sync(0xffffffffu, idx, t + 2);
                int u3 = __shfl_sync(0xffffffffu, idx, t + 3);
                float4 v0 = *(const float4*)&in[(long)u0 * stride + lane * 4];
                float4 v1 = *(const float4*)&in[(long)u1 * stride + lane * 4];
                float4 v2 = *(const float4*)&in[(long)u2 * stride + lane * 4];
                float4 v3 = *(const float4*)&in[(long)u3 * stride + lane * 4];
                acc.x += (v0.x + v1.x) + (v2.x + v3.x);
                acc.y += (v0.y + v1.y) + (v2.y + v3.y);
                acc.z += (v0.z + v1.z) + (v2.z + v3.z);
                acc.w += (v0.w + v1.w) + (v2.w + v3.w);
            }
            for (; t < n; t++) {
                int u = __shfl_sync(0xffffffffu, idx, t);
                float4 v = *(const float4*)&in[(long)u * stride + lane * 4];
                acc.x += v.x; acc.y += v.y; acc.z += v.z; acc.w += v.w;
            }
        }
        *(float4*)&g_agg[(long)warp * F + lane * 4] = acc;
    } else {
        float2 acc = make_float2(0.f, 0.f);
        for (int j = beg; j < end; j += 32) {
            int n = min(32, end - j);
            int idx = (lane < n) ? g_csr[j + lane] : 0;
            int t = 0;
            for (; t + 4 <= n; t += 4) {
                int u0 = __shfl_sync(0xffffffffu, idx, t + 0);
                int u1 = __shfl_sync(0xffffffffu, idx, t + 1);
                int u2 = __shfl_sync(0xffffffffu, idx, t + 2);
                int u3 = __shfl_sync(0xffffffffu, idx, t + 3);
                float2 v0 = *(const float2*)&in[(long)u0 * stride + lane * 2];
                float2 v1 = *(const float2*)&in[(long)u1 * stride + lane * 2];
                float2 v2 = *(const float2*)&in[(long)u2 * stride + lane * 2];
                float2 v3 = *(const float2*)&in[(long)u3 * stride + lane * 2];
                acc.x += (v0.x + v1.x) + (v2.x + v3.x);
                acc.y += (v0.y + v1.y) + (v2.y + v3.y);
            }
            for (; t < n; t++) {
                int u = __shfl_sync(0xffffffffu, idx, t);
                float2 v = *(const float2*)&in[(long)u * stride + lane * 2];
                acc.x += v.x; acc.y += v.y;
            }
        }
        *(float2*)&g_agg[(long)warp * F + lane * 2] = acc;
    }
}

// ---------------- fused GIN MLP: h = relu(relu(((1+eps)x+agg)W1+b1)W2+b2) ---
// Tile: 64 nodes x 64 outputs, 256 threads as 16x16, 4x4 microtiles.
__global__ void __launch_bounds__(256) k_mlp(const float* __restrict__ x,
                                             int use_x, int in_off, int fin,
                                             const float* __restrict__ eps, int layer,
                                             const float* __restrict__ W1,
                                             const float* __restrict__ B1,
                                             const float* __restrict__ W2,
                                             const float* __restrict__ B2,
                                             int out_off) {
    __shared__ float sA[64][68];
    __shared__ float sB[64][68];

    const int tid = threadIdx.x;
    const int tx = tid & 15;
    const int ty = tid >> 4;
    const int tile = blockIdx.x * 64;

    const float* in = use_x ? x : (g_hs + in_off);
    const int in_stride = use_x ? FIN : HS;
    const float epsv = 1.0f + eps[layer];

    float4 c0 = make_float4(0.f, 0.f, 0.f, 0.f), c1 = c0, c2 = c0, c3 = c0;

    for (int kc = 0; kc < fin; kc += 64) {
#pragma unroll
        for (int s = 0; s < 4; s++) {
            int slot = tid + s * 256;
            int r  = slot >> 4;
            int k4 = slot & 15;
            int rg = tile + r;
            float4 v = make_float4(0.f, 0.f, 0.f, 0.f);
            if (rg < NN) {
                float4 xv = *(const float4*)&in[(long)rg * in_stride + kc + k4 * 4];
                float4 av = *(const float4*)&g_agg[(long)rg * fin + kc + k4 * 4];
                v.x = epsv * xv.x + av.x;
                v.y = epsv * xv.y + av.y;
                v.z = epsv * xv.z + av.z;
                v.w = epsv * xv.w + av.w;
            }
            *(float4*)&sA[r][k4 * 4] = v;
            *(float4*)&sB[r][k4 * 4] = *(const float4*)&W1[(long)(kc + r) * 64 + k4 * 4];
        }
        __syncthreads();
#pragma unroll 8
        for (int k = 0; k < 64; k++) {
            float4 b = *(const float4*)&sB[k][tx * 4];
            float a0 = sA[ty * 4 + 0][k];
            float a1 = sA[ty * 4 + 1][k];
            float a2 = sA[ty * 4 + 2][k];
            float a3 = sA[ty * 4 + 3][k];
            c0.x += a0 * b.x; c0.y += a0 * b.y; c0.z += a0 * b.z; c0.w += a0 * b.w;
            c1.x += a1 * b.x; c1.y += a1 * b.y; c1.z += a1 * b.z; c1.w += a1 * b.w;
            c2.x += a2 * b.x; c2.y += a2 * b.y; c2.z += a2 * b.z; c2.w += a2 * b.w;
            c3.x += a3 * b.x; c3.y += a3 * b.y; c3.z += a3 * b.z; c3.w += a3 * b.w;
        }
        __syncthreads();
    }

    {
        float4 bb = *(const float4*)&B1[tx * 4];
        float4 h;
        h.x = fmaxf(c0.x + bb.x, 0.f); h.y = fmaxf(c0.y + bb.y, 0.f);
        h.z = fmaxf(c0.z + bb.z, 0.f); h.w = fmaxf(c0.w + bb.w, 0.f);
        *(float4*)&sA[ty * 4 + 0][tx * 4] = h;
        h.x = fmaxf(c1.x + bb.x, 0.f); h.y = fmaxf(c1.y + bb.y, 0.f);
        h.z = fmaxf(c1.z + bb.z, 0.f); h.w = fmaxf(c1.w + bb.w, 0.f);
        *(float4*)&sA[ty * 4 + 1][tx * 4] = h;
        h.x = fmaxf(c2.x + bb.x, 0.f); h.y = fmaxf(c2.y + bb.y, 0.f);
        h.z = fmaxf(c2.z + bb.z, 0.f); h.w = fmaxf(c2.w + bb.w, 0.f);
        *(float4*)&sA[ty * 4 + 2][tx * 4] = h;
        h.x = fmaxf(c3.x + bb.x, 0.f); h.y = fmaxf(c3.y + bb.y, 0.f);
        h.z = fmaxf(c3.z + bb.z, 0.f); h.w = fmaxf(c3.w + bb.w, 0.f);
        *(float4*)&sA[ty * 4 + 3][tx * 4] = h;
    }
#pragma unroll
    for (int s = 0; s < 4; s++) {
        int slot = tid + s * 256;
        int r  = slot >> 4;
        int k4 = slot & 15;
        *(float4*)&sB[r][k4 * 4] = *(const float4*)&W2[(long)r * 64 + k4 * 4];
    }
    __syncthreads();

    c0 = make_float4(0.f, 0.f, 0.f, 0.f); c1 = c0; c2 = c0; c3 = c0;
#pragma unroll 8
    for (int k = 0; k < 64; k++) {
        float4 b = *(const float4*)&sB[k][tx * 4];
        float a0 = sA[ty * 4 + 0][k];
        float a1 = sA[ty * 4 + 1][k];
        float a2 = sA[ty * 4 + 2][k];
        float a3 = sA[ty * 4 + 3][k];
        c0.x += a0 * b.x; c0.y += a0 * b.y; c0.z += a0 * b.z; c0.w += a0 * b.w;
        c1.x += a1 * b.x; c1.y += a1 * b.y; c1.z += a1 * b.z; c1.w += a1 * b.w;
        c2.x += a2 * b.x; c2.y += a2 * b.y; c2.z += a2 * b.z; c2.w += a2 * b.w;
        c3.x += a3 * b.x; c3.y += a3 * b.y; c3.z += a3 * b.z; c3.w += a3 * b.w;
    }

    {
        float4 bb = *(const float4*)&B2[tx * 4];
        float4 o;
        int rg;
        rg = tile + ty * 4 + 0;
        if (rg < NN) {
            o.x = fmaxf(c0.x + bb.x, 0.f); o.y = fmaxf(c0.y + bb.y, 0.f);
            o.z = fmaxf(c0.z + bb.z, 0.f); o.w = fmaxf(c0.w + bb.w, 0.f);
            *(float4*)&g_hs[(long)rg * HS + out_off + tx * 4] = o;
        }
        rg = tile + ty * 4 + 1;
        if (rg < NN) {
            o.x = fmaxf(c1.x + bb.x, 0.f); o.y = fmaxf(c1.y + bb.y, 0.f);
            o.z = fmaxf(c1.z + bb.z, 0.f); o.w = fmaxf(c1.w + bb.w, 0.f);
            *(float4*)&g_hs[(long)rg * HS + out_off + tx * 4] = o;
        }
        rg = tile + ty * 4 + 2;
        if (rg < NN) {
            o.x = fmaxf(c2.x + bb.x, 0.f); o.y = fmaxf(c2.y + bb.y, 0.f);
            o.z = fmaxf(c2.z + bb.z, 0.f); o.w = fmaxf(c2.w + bb.w, 0.f);
            *(float4*)&g_hs[(long)rg * HS + out_off + tx * 4] = o;
        }
        rg = tile + ty * 4 + 3;
        if (rg < NN) {
            o.x = fmaxf(c3.x + bb.x, 0.f); o.y = fmaxf(c3.y + bb.y, 0.f);
            o.z = fmaxf(c3.z + bb.z, 0.f); o.w = fmaxf(c3.w + bb.w, 0.f);
            *(float4*)&g_hs[(long)rg * HS + out_off + tx * 4] = o;
        }
    }
}

// ---------------- graph segment bookkeeping (batch is sorted) --------------
__global__ void k_zero_cnt() {
    int i = blockIdx.x * 256 + threadIdx.x;
    if (i < NG) g_cnt[i] = 0;
}

__global__ void k_count(const void* __restrict__ batch) {
    int i = blockIdx.x * 256 + threadIdx.x;
    if (i < NN) atomicAdd(&g_cnt[(int)ld_idx(batch, i)], 1);
}

__global__ void k_offsets() {
    if (threadIdx.x == 0) {
        int a = 0;
        for (int i = 0; i < NG; i++) { g_off[i] = a; a += g_cnt[i]; }
        g_off[NG] = a;
    }
}

// ---------------- readout: mean/max/sum per graph + fc1 + fc2 + sigmoid ----
__global__ void __launch_bounds__(192) k_readout(const float* __restrict__ fc1w,
                                                 const float* __restrict__ fc1b,
                                                 const float* __restrict__ fc2w,
                                                 const float* __restrict__ fc2b,
                                                 float* __restrict__ out) {
    __shared__ float gv[GF];
    __shared__ float q[HH];

    int g = blockIdx.x;
    int f = threadIdx.x;
    int n0 = g_off[g], n1 = g_off[g + 1];

    float s = 0.f, m = -3.402823466e38f;
    for (int n = n0; n < n1; n++) {
        float v = g_hs[(long)n * HS + f];
        s += v;
        m = fmaxf(m, v);
    }
    int cnt = n1 - n0;
    gv[f]       = s / fmaxf((float)cnt, 1.f);
    gv[192 + f] = m;
    gv[384 + f] = s;
    __syncthreads();

    if (f < HH) {
        float a = fc1b[f];
#pragma unroll 4
        for (int k = 0; k < GF; k++) a += gv[k] * fc1w[k * 64 + f];
        q[f] = fmaxf(a, 0.f);
    }
    __syncthreads();

    if (f < 2) {
        float a = fc2b[f];
#pragma unroll
        for (int k = 0; k < HH; k++) a += q[k] * fc2w[k * 2 + f];
        out[g * 2 + f] = 1.f / (1.f + expf(-a));
    }
}

// ---------------- launch ----------------------------------------------------
extern "C" void kernel_launch(void* const* d_in, const int* in_sizes, int n_in,
                              void* d_out, int out_size) {
    const float* x     = (const float*)d_in[0];
    const void*  edge  = d_in[1];
    const void*  batch = d_in[2];
    const float* w1[3] = {(const float*)d_in[3],  (const float*)d_in[7],  (const float*)d_in[11]};
    const float* b1[3] = {(const float*)d_in[4],  (const float*)d_in[8],  (const float*)d_in[12]};
    const float* w2[3] = {(const float*)d_in[5],  (const float*)d_in[9],  (const float*)d_in[13]};
    const float* b2[3] = {(const float*)d_in[6],  (const float*)d_in[10], (const float*)d_in[14]};
    const float* eps   = (const float*)d_in[15];
    const float* fc1w  = (const float*)d_in[16];
    const float* fc1b  = (const float*)d_in[17];
    const float* fc2w  = (const float*)d_in[18];
    const float* fc2b  = (const float*)d_in[19];

    k_detect<<<1, 32>>>(edge);

    // CSR build (once; reused by all 3 layers)
    k_zero_deg<<<(NN + 255) / 256, 256>>>();
    k_deg<<<(NE + 255) / 256, 256>>>(edge);
    k_scan<<<1, 1024>>>();
    k_init_cursor<<<(NN + 255) / 256, 256>>>();
    k_fill<<<(NE + 255) / 256, 256>>>(edge);

    const int pull_grid = (NN + 7) / 8;   // 8 warps per 256-thread block

    for (int L = 0; L < 3; L++) {
        const int fin  = (L == 0) ? FIN : HH;
        const int usex = (L == 0) ? 1 : 0;
        const int inoff = (L == 0) ? 0 : (L - 1) * 64;

        if (L == 0) {
            k_pull<FIN><<<pull_grid, 256>>>(x, 1, 0);
        } else {
            k_pull<HH><<<pull_grid, 256>>>(x, 0, inoff);
        }

        k_mlp<<<(NN + 63) / 64, 256>>>(x, usex, inoff, fin, eps, L,
                                       w1[L], b1[L], w2[L], b2[L], L * 64);
    }

    k_zero_cnt<<<2, 256>>>();
    k_count<<<(NN + 255) / 256, 256>>>(batch);
    k_offsets<<<1, 32>>>();
    k_readout<<<NG, 192>>>(fc1w, fc1b, fc2w, fc2b, (float*)d_out);
}

// round 4
// speedup vs baseline: 1.4934x; 1.2875x over previous
#include <cuda_runtime.h>
#include <math.h>

// Problem constants (fixed shapes)
#define NN 100000
#define NE 1600000
#define NG 512
#define FIN 128
#define HH 64
#define HS 192   // 3*H concat width
#define GF 576   // 3*HS graph feature width

#define SCAN_CH 1024
#define NSB ((NN + SCAN_CH - 1) / SCAN_CH)   // 98 scan blocks

// ---------------- scratch (static device globals; no runtime alloc) -------
__device__ __align__(16) float g_agg[(size_t)NN * FIN];   // 51.2 MB
__device__ __align__(16) float g_hs[(size_t)NN * HS];     // 76.8 MB
__device__ __align__(16) int g_rowptr[NN + 4];
__device__ __align__(16) int g_cursor[NN + 4];   // degree accumulator, then fill cursor
__device__ int g_csr[NE];
__device__ int g_bsum[NSB];
__device__ int g_boff[NSB + 1];
__device__ int g_cnt[NG];
__device__ int g_off[NG + 1];
__device__ int g_is64;

// ---------------- index dtype handling -------------------------------------
__device__ __forceinline__ long ld_idx(const void* p, long i) {
    if (g_is64) return (long)((const long long*)p)[i];
    return (long)((const int*)p)[i];
}

__global__ void k_detect(const void* edge) {
    // int64 indices < 2^31 => every odd 32-bit word is zero. Warp-parallel probe.
    const int* p = (const int*)edge;
    int t = threadIdx.x;
    int nz = (p[2 * t + 1] != 0) ? 1 : 0;
    unsigned m = __ballot_sync(0xffffffffu, nz);
    if (t == 0) g_is64 = (m == 0) ? 1 : 0;
}

// ---------------- CSR build (once per launch; reused by all 3 layers) ------
__global__ void k_zero_deg() {
    int i = blockIdx.x * 256 + threadIdx.x;
    if (i < NN) g_cursor[i] = 0;
}

__global__ void k_deg(const void* __restrict__ edge) {
    long e = (long)blockIdx.x * 256 + threadIdx.x;
    if (e < NE) {
        int d = (int)ld_idx(edge, (long)NE + e);
        atomicAdd(&g_cursor[d], 1);
    }
}

// Pass 1: per-block sums of 1024 degrees (256 threads x int4).
__global__ void __launch_bounds__(256) k_bsum() {
    __shared__ int ws[8];
    const int b = blockIdx.x, t = threadIdx.x;
    const int base = b * SCAN_CH + t * 4;
    int s = 0;
    if (base < NN) {                       // NN%4==0 => whole int4 in range
        int4 v = *(const int4*)&g_cursor[base];
        s = (v.x + v.y) + (v.z + v.w);
    }
#pragma unroll
    for (int o = 16; o > 0; o >>= 1) s += __shfl_down_sync(0xffffffffu, s, o);
    if ((t & 31) == 0) ws[t >> 5] = s;
    __syncthreads();
    if (t < 8) {
        int v = ws[t];
#pragma unroll
        for (int o = 4; o > 0; o >>= 1) v += __shfl_down_sync(0xffu, v, o);
        if (t == 0) g_bsum[b] = v;
    }
}

// Pass 2: scan the 98 block sums in one tiny block.
__global__ void __launch_bounds__(128) k_bscan() {
    __shared__ int s[128];
    int t = threadIdx.x;
    int v = (t < NSB) ? g_bsum[t] : 0;
    s[t] = v;
    __syncthreads();
#pragma unroll
    for (int d = 1; d < 128; d <<= 1) {
        int u = (t >= d) ? s[t - d] : 0;
        __syncthreads();
        s[t] += u;
        __syncthreads();
    }
    g_boff[t] = (t == 0) ? 0 : s[t - 1];
    if (t == NSB - 1) g_rowptr[NN] = s[t];
}

// Pass 3: per-block rescan -> rowptr, and initialize fill cursor in one pass.
__global__ void __launch_bounds__(256) k_rowptr() {
    __shared__ int s[256];
    const int b = blockIdx.x, t = threadIdx.x;
    const int base = b * SCAN_CH + t * 4;
    int d0 = 0, d1 = 0, d2 = 0, d3 = 0;
    if (base < NN) {
        int4 v = *(const int4*)&g_cursor[base];
        d0 = v.x; d1 = v.y; d2 = v.z; d3 = v.w;
    }
    s[t] = d0 + d1 + d2 + d3;
    __syncthreads();
#pragma unroll
    for (int d = 1; d < 256; d <<= 1) {
        int u = (t >= d) ? s[t - d] : 0;
        __syncthreads();
        s[t] += u;
        __syncthreads();
    }
    int off = g_boff[b] + ((t == 0) ? 0 : s[t - 1]);
    if (base < NN) {
        int4 r;
        r.x = off;
        r.y = off + d0;
        r.z = off + d0 + d1;
        r.w = off + d0 + d1 + d2;
        *(int4*)&g_rowptr[base] = r;
        *(int4*)&g_cursor[base] = r;   // cursor init fused
    }
}

__global__ void k_fill(const void* __restrict__ edge) {
    long e = (long)blockIdx.x * 256 + threadIdx.x;
    if (e < NE) {
        int s = (int)ld_idx(edge, e);
        int d = (int)ld_idx(edge, (long)NE + e);
        int pos = atomicAdd(&g_cursor[d], 1);
        g_csr[pos] = s;
    }
}

// ---------------- pull-aggregation -----------------------------------------
// One warp per destination node: sum neighbor feature rows with plain loads.
template <int F>
__global__ void __launch_bounds__(256) k_pull(const float* __restrict__ x,
                                              int use_x, int in_off) {
    const float* in = use_x ? x : (g_hs + in_off);
    const int stride = use_x ? FIN : HS;

    int warp = (blockIdx.x * 256 + threadIdx.x) >> 5;
    int lane = threadIdx.x & 31;
    if (warp >= NN) return;
    int beg = g_rowptr[warp], end = g_rowptr[warp + 1];

    if (F == 128) {
        float4 acc = make_float4(0.f, 0.f, 0.f, 0.f);
        for (int j = beg; j < end; j += 32) {
            int n = min(32, end - j);
            int idx = (lane < n) ? g_csr[j + lane] : 0;
            int t = 0;
            for (; t + 4 <= n; t += 4) {
                int u0 = __shfl_sync(0xffffffffu, idx, t + 0);
                int u1 = __shfl_sync(0xffffffffu, idx, t + 1);
                int u2 = __shfl_sync(0xffffffffu, idx, t + 2);
                int u3 = __shfl_sync(0xffffffffu, idx, t + 3);
                float4 v0 = *(const float4*)&in[(long)u0 * stride + lane * 4];
                float4 v1 = *(const float4*)&in[(long)u1 * stride + lane * 4];
                float4 v2 = *(const float4*)&in[(long)u2 * stride + lane * 4];
                float4 v3 = *(const float4*)&in[(long)u3 * stride + lane * 4];
                acc.x += (v0.x + v1.x) + (v2.x + v3.x);
                acc.y += (v0.y + v1.y) + (v2.y + v3.y);
                acc.z += (v0.z + v1.z) + (v2.z + v3.z);
                acc.w += (v0.w + v1.w) + (v2.w + v3.w);
            }
            for (; t < n; t++) {
                int u = __shfl_sync(0xffffffffu, idx, t);
                float4 v = *(const float4*)&in[(long)u * stride + lane * 4];
                acc.x += v.x; acc.y += v.y; acc.z += v.z; acc.w += v.w;
            }
        }
        *(float4*)&g_agg[(long)warp * F + lane * 4] = acc;
    } else {
        float2 acc = make_float2(0.f, 0.f);
        for (int j = beg; j < end; j += 32) {
            int n = min(32, end - j);
            int idx = (lane < n) ? g_csr[j + lane] : 0;
            int t = 0;
            for (; t + 4 <= n; t += 4) {
                int u0 = __shfl_sync(0xffffffffu, idx, t + 0);
                int u1 = __shfl_sync(0xffffffffu, idx, t + 1);
                int u2 = __shfl_sync(0xffffffffu, idx, t + 2);
                int u3 = __shfl_sync(0xffffffffu, idx, t + 3);
                float2 v0 = *(const float2*)&in[(long)u0 * stride + lane * 2];
                float2 v1 = *(const float2*)&in[(long)u1 * stride + lane * 2];
                float2 v2 = *(const float2*)&in[(long)u2 * stride + lane * 2];
                float2 v3 = *(const float2*)&in[(long)u3 * stride + lane * 2];
                acc.x += (v0.x + v1.x) + (v2.x + v3.x);
                acc.y += (v0.y + v1.y) + (v2.y + v3.y);
            }
            for (; t < n; t++) {
                int u = __shfl_sync(0xffffffffu, idx, t);
                float2 v = *(const float2*)&in[(long)u * stride + lane * 2];
                acc.x += v.x; acc.y += v.y;
            }
        }
        *(float2*)&g_agg[(long)warp * F + lane * 2] = acc;
    }
}

// ---------------- fused GIN MLP: h = relu(relu(((1+eps)x+agg)W1+b1)W2+b2) ---
__global__ void __launch_bounds__(256) k_mlp(const float* __restrict__ x,
                                             int use_x, int in_off, int fin,
                                             const float* __restrict__ eps, int layer,
                                             const float* __restrict__ W1,
                                             const float* __restrict__ B1,
                                             const float* __restrict__ W2,
                                             const float* __restrict__ B2,
                                             int out_off) {
    __shared__ float sA[64][68];
    __shared__ float sB[64][68];

    const int tid = threadIdx.x;
    const int tx = tid & 15;
    const int ty = tid >> 4;
    const int tile = blockIdx.x * 64;

    const float* in = use_x ? x : (g_hs + in_off);
    const int in_stride = use_x ? FIN : HS;
    const float epsv = 1.0f + eps[layer];

    float4 c0 = make_float4(0.f, 0.f, 0.f, 0.f), c1 = c0, c2 = c0, c3 = c0;

    for (int kc = 0; kc < fin; kc += 64) {
#pragma unroll
        for (int s = 0; s < 4; s++) {
            int slot = tid + s * 256;
            int r  = slot >> 4;
            int k4 = slot & 15;
            int rg = tile + r;
            float4 v = make_float4(0.f, 0.f, 0.f, 0.f);
            if (rg < NN) {
                float4 xv = *(const float4*)&in[(long)rg * in_stride + kc + k4 * 4];
                float4 av = *(const float4*)&g_agg[(long)rg * fin + kc + k4 * 4];
                v.x = epsv * xv.x + av.x;
                v.y = epsv * xv.y + av.y;
                v.z = epsv * xv.z + av.z;
                v.w = epsv * xv.w + av.w;
            }
            *(float4*)&sA[r][k4 * 4] = v;
            *(float4*)&sB[r][k4 * 4] = *(const float4*)&W1[(long)(kc + r) * 64 + k4 * 4];
        }
        __syncthreads();
#pragma unroll 8
        for (int k = 0; k < 64; k++) {
            float4 b = *(const float4*)&sB[k][tx * 4];
            float a0 = sA[ty * 4 + 0][k];
            float a1 = sA[ty * 4 + 1][k];
            float a2 = sA[ty * 4 + 2][k];
            float a3 = sA[ty * 4 + 3][k];
            c0.x += a0 * b.x; c0.y += a0 * b.y; c0.z += a0 * b.z; c0.w += a0 * b.w;
            c1.x += a1 * b.x; c1.y += a1 * b.y; c1.z += a1 * b.z; c1.w += a1 * b.w;
            c2.x += a2 * b.x; c2.y += a2 * b.y; c2.z += a2 * b.z; c2.w += a2 * b.w;
            c3.x += a3 * b.x; c3.y += a3 * b.y; c3.z += a3 * b.z; c3.w += a3 * b.w;
        }
        __syncthreads();
    }

    {
        float4 bb = *(const float4*)&B1[tx * 4];
        float4 h;
        h.x = fmaxf(c0.x + bb.x, 0.f); h.y = fmaxf(c0.y + bb.y, 0.f);
        h.z = fmaxf(c0.z + bb.z, 0.f); h.w = fmaxf(c0.w + bb.w, 0.f);
        *(float4*)&sA[ty * 4 + 0][tx * 4] = h;
        h.x = fmaxf(c1.x + bb.x, 0.f); h.y = fmaxf(c1.y + bb.y, 0.f);
        h.z = fmaxf(c1.z + bb.z, 0.f); h.w = fmaxf(c1.w + bb.w, 0.f);
        *(float4*)&sA[ty * 4 + 1][tx * 4] = h;
        h.x = fmaxf(c2.x + bb.x, 0.f); h.y = fmaxf(c2.y + bb.y, 0.f);
        h.z = fmaxf(c2.z + bb.z, 0.f); h.w = fmaxf(c2.w + bb.w, 0.f);
        *(float4*)&sA[ty * 4 + 2][tx * 4] = h;
        h.x = fmaxf(c3.x + bb.x, 0.f); h.y = fmaxf(c3.y + bb.y, 0.f);
        h.z = fmaxf(c3.z + bb.z, 0.f); h.w = fmaxf(c3.w + bb.w, 0.f);
        *(float4*)&sA[ty * 4 + 3][tx * 4] = h;
    }
#pragma unroll
    for (int s = 0; s < 4; s++) {
        int slot = tid + s * 256;
        int r  = slot >> 4;
        int k4 = slot & 15;
        *(float4*)&sB[r][k4 * 4] = *(const float4*)&W2[(long)r * 64 + k4 * 4];
    }
    __syncthreads();

    c0 = make_float4(0.f, 0.f, 0.f, 0.f); c1 = c0; c2 = c0; c3 = c0;
#pragma unroll 8
    for (int k = 0; k < 64; k++) {
        float4 b = *(const float4*)&sB[k][tx * 4];
        float a0 = sA[ty * 4 + 0][k];
        float a1 = sA[ty * 4 + 1][k];
        float a2 = sA[ty * 4 + 2][k];
        float a3 = sA[ty * 4 + 3][k];
        c0.x += a0 * b.x; c0.y += a0 * b.y; c0.z += a0 * b.z; c0.w += a0 * b.w;
        c1.x += a1 * b.x; c1.y += a1 * b.y; c1.z += a1 * b.z; c1.w += a1 * b.w;
        c2.x += a2 * b.x; c2.y += a2 * b.y; c2.z += a2 * b.z; c2.w += a2 * b.w;
        c3.x += a3 * b.x; c3.y += a3 * b.y; c3.z += a3 * b.z; c3.w += a3 * b.w;
    }

    {
        float4 bb = *(const float4*)&B2[tx * 4];
        float4 o;
        int rg;
        rg = tile + ty * 4 + 0;
        if (rg < NN) {
            o.x = fmaxf(c0.x + bb.x, 0.f); o.y = fmaxf(c0.y + bb.y, 0.f);
            o.z = fmaxf(c0.z + bb.z, 0.f); o.w = fmaxf(c0.w + bb.w, 0.f);
            *(float4*)&g_hs[(long)rg * HS + out_off + tx * 4] = o;
        }
        rg = tile + ty * 4 + 1;
        if (rg < NN) {
            o.x = fmaxf(c1.x + bb.x, 0.f); o.y = fmaxf(c1.y + bb.y, 0.f);
            o.z = fmaxf(c1.z + bb.z, 0.f); o.w = fmaxf(c1.w + bb.w, 0.f);
            *(float4*)&g_hs[(long)rg * HS + out_off + tx * 4] = o;
        }
        rg = tile + ty * 4 + 2;
        if (rg < NN) {
            o.x = fmaxf(c2.x + bb.x, 0.f); o.y = fmaxf(c2.y + bb.y, 0.f);
            o.z = fmaxf(c2.z + bb.z, 0.f); o.w = fmaxf(c2.w + bb.w, 0.f);
            *(float4*)&g_hs[(long)rg * HS + out_off + tx * 4] = o;
        }
        rg = tile + ty * 4 + 3;
        if (rg < NN) {
            o.x = fmaxf(c3.x + bb.x, 0.f); o.y = fmaxf(c3.y + bb.y, 0.f);
            o.z = fmaxf(c3.z + bb.z, 0.f); o.w = fmaxf(c3.w + bb.w, 0.f);
            *(float4*)&g_hs[(long)rg * HS + out_off + tx * 4] = o;
        }
    }
}

// ---------------- graph segment bookkeeping (batch is sorted) --------------
__global__ void k_zero_cnt() {
    int i = blockIdx.x * 256 + threadIdx.x;
    if (i < NG) g_cnt[i] = 0;
}

__global__ void k_count(const void* __restrict__ batch) {
    int i = blockIdx.x * 256 + threadIdx.x;
    if (i < NN) atomicAdd(&g_cnt[(int)ld_idx(batch, i)], 1);
}

__global__ void __launch_bounds__(512) k_offsets() {
    __shared__ int s[NG];
    int t = threadIdx.x;
    s[t] = g_cnt[t];
    __syncthreads();
#pragma unroll
    for (int d = 1; d < NG; d <<= 1) {
        int u = (t >= d) ? s[t - d] : 0;
        __syncthreads();
        s[t] += u;
        __syncthreads();
    }
    g_off[t] = (t == 0) ? 0 : s[t - 1];
    if (t == NG - 1) g_off[NG] = s[t];
}

// ---------------- readout: mean/max/sum per graph + fc1 + fc2 + sigmoid ----
__global__ void __launch_bounds__(192) k_readout(const float* __restrict__ fc1w,
                                                 const float* __restrict__ fc1b,
                                                 const float* __restrict__ fc2w,
                                                 const float* __restrict__ fc2b,
                                                 float* __restrict__ out) {
    __shared__ float gv[GF];
    __shared__ float q[HH];

    int g = blockIdx.x;
    int f = threadIdx.x;
    int n0 = g_off[g], n1 = g_off[g + 1];

    float s = 0.f, m = -3.402823466e38f;
    for (int n = n0; n < n1; n++) {
        float v = g_hs[(long)n * HS + f];
        s += v;
        m = fmaxf(m, v);
    }
    int cnt = n1 - n0;
    gv[f]       = s / fmaxf((float)cnt, 1.f);
    gv[192 + f] = m;
    gv[384 + f] = s;
    __syncthreads();

    if (f < HH) {
        float a = fc1b[f];
#pragma unroll 4
        for (int k = 0; k < GF; k++) a += gv[k] * fc1w[k * 64 + f];
        q[f] = fmaxf(a, 0.f);
    }
    __syncthreads();

    if (f < 2) {
        float a = fc2b[f];
#pragma unroll
        for (int k = 0; k < HH; k++) a += q[k] * fc2w[k * 2 + f];
        out[g * 2 + f] = 1.f / (1.f + expf(-a));
    }
}

// ---------------- launch ----------------------------------------------------
extern "C" void kernel_launch(void* const* d_in, const int* in_sizes, int n_in,
                              void* d_out, int out_size) {
    const float* x     = (const float*)d_in[0];
    const void*  edge  = d_in[1];
    const void*  batch = d_in[2];
    const float* w1[3] = {(const float*)d_in[3],  (const float*)d_in[7],  (const float*)d_in[11]};
    const float* b1[3] = {(const float*)d_in[4],  (const float*)d_in[8],  (const float*)d_in[12]};
    const float* w2[3] = {(const float*)d_in[5],  (const float*)d_in[9],  (const float*)d_in[13]};
    const float* b2[3] = {(const float*)d_in[6],  (const float*)d_in[10], (const float*)d_in[14]};
    const float* eps   = (const float*)d_in[15];
    const float* fc1w  = (const float*)d_in[16];
    const float* fc1b  = (const float*)d_in[17];
    const float* fc2w  = (const float*)d_in[18];
    const float* fc2b  = (const float*)d_in[19];

    k_detect<<<1, 32>>>(edge);

    // CSR build (once; reused by all 3 layers)
    k_zero_deg<<<(NN + 255) / 256, 256>>>();
    k_deg<<<(NE + 255) / 256, 256>>>(edge);
    k_bsum<<<NSB, 256>>>();
    k_bscan<<<1, 128>>>();
    k_rowptr<<<NSB, 256>>>();
    k_fill<<<(NE + 255) / 256, 256>>>(edge);

    const int pull_grid = (NN + 7) / 8;   // 8 warps per 256-thread block

    for (int L = 0; L < 3; L++) {
        const int fin  = (L == 0) ? FIN : HH;
        const int usex = (L == 0) ? 1 : 0;
        const int inoff = (L == 0) ? 0 : (L - 1) * 64;

        if (L == 0) {
            k_pull<FIN><<<pull_grid, 256>>>(x, 1, 0);
        } else {
            k_pull<HH><<<pull_grid, 256>>>(x, 0, inoff);
        }

        k_mlp<<<(NN + 63) / 64, 256>>>(x, usex, inoff, fin, eps, L,
                                       w1[L], b1[L], w2[L], b2[L], L * 64);
    }

    k_zero_cnt<<<2, 256>>>();
    k_count<<<(NN + 255) / 256, 256>>>(batch);
    k_offsets<<<1, NG>>>();
    k_readout<<<NG, 192>>>(fc1w, fc1b, fc2w, fc2b, (float*)d_out);
}